// round 2
// baseline (speedup 1.0000x reference)
#include <cuda_runtime.h>
#include <cstdint>

// Moment feature expansion, order 4, latent dim 16.
// out[b,t,:] = [1, x(16), f2(136), f3(816), f4(3876)] -> 4845 channels.
// Round 2: 8 rows/block (L1-resident index tables), full row staged in a
// phase-shifted smem buffer so the flush is scalar-head + aligned float4
// body + scalar-tail (clean 4-sector store wavefronts, 4x fewer STG).

#define D    16
#define N2   136
#define N3   816
#define N4   3876
#define NOUT 4845   // 1 + 16 + 136 + 816 + 3876
#define OFF1 1
#define OFF2 17     // 1 + 16
#define OFF3 153    // 1 + 16 + 136
#define OFF4 969    // 1 + 16 + 136 + 816

#define RPB      8
#define NTHREADS 256

struct Tab2 { uint16_t v[N2]; };
struct Tab3 { uint16_t v[N3]; };
struct Tab4 { uint16_t v[N4]; };

// Order-2: pairs (k, j) with 0 <= j <= k < 16, k-major.
constexpr Tab2 gen2() {
    Tab2 t{}; int m = 0;
    for (int k = 0; k < D; k++)
        for (int j = 0; j <= k; j++)
            t.v[m++] = (uint16_t)((k << 4) | j);
    return t;
}

// Order-3: offsets2[j] = 136 - (16-j)(17-j)/2 ; keep (k,j) iff k >= offsets2[j].
constexpr Tab3 gen3() {
    Tab3 t{}; int m = 0;
    int off[D] = {};
    for (int j = 0; j < D; j++)
        off[j] = N2 - (D - j) * (D - j + 1) / 2;
    for (int k = 0; k < N2; k++)
        for (int j = 0; j < D; j++)
            if (k >= off[j]) t.v[m++] = (uint16_t)((k << 4) | j);
    return t;
}

// Order-4: offsets3[j] = 816 - C(18-j, 3) ; keep (k,j) iff k >= offsets3[j].
constexpr Tab4 gen4() {
    Tab4 t{}; int m = 0;
    int off[D] = {};
    for (int j = 0; j < D; j++) {
        int a = D + 2 - j;                      // 18 - j
        off[j] = N3 - a * (a - 1) * (a - 2) / 6;
    }
    for (int k = 0; k < N3; k++)
        for (int j = 0; j < D; j++)
            if (k >= off[j]) t.v[m++] = (uint16_t)((k << 4) | j);
    return t;
}

__device__ constexpr Tab2 c_t2 = gen2();
__device__ constexpr Tab3 c_t3 = gen3();
__device__ constexpr Tab4 c_t4 = gen4();

__global__ __launch_bounds__(NTHREADS)
void Moment_2774548873409_kernel(const float* __restrict__ in,
                                 float* __restrict__ out,
                                 int rows) {
    // Full-row staging buffer, +4 slack for the mod-4 phase shift.
    __shared__ __align__(16) float sf[NOUT + 4];

    const int t = threadIdx.x;
    const int row0 = blockIdx.x * RPB;

    #pragma unroll 1
    for (int rr = 0; rr < RPB; rr++) {
        const int row = row0 + rr;
        if (row >= rows) break;

        const size_t gbase = (size_t)row * NOUT;
        // 4845 % 4 == 1, so gbase % 4 == row % 4.
        const int shift = (int)(gbase & 3);   // smem idx = shift + channel
        const float* __restrict__ xin = in + (size_t)row * D;

        // --- orders 0, 1 ---
        if (t == 0) sf[shift] = 1.0f;
        if (t < D)  sf[shift + OFF1 + t] = xin[t];
        __syncthreads();

        // --- order 2: f2[m] = x[k] * x[j] ---
        if (t < N2) {
            const uint16_t p = c_t2.v[t];
            sf[shift + OFF2 + t] =
                sf[shift + OFF1 + (p >> 4)] * sf[shift + OFF1 + (p & 15)];
        }
        __syncthreads();

        // --- order 3: f3[m] = f2[k] * x[j] ---
        #pragma unroll
        for (int m = t; m < N3; m += NTHREADS) {
            const uint16_t p = c_t3.v[m];
            sf[shift + OFF3 + m] =
                sf[shift + OFF2 + (p >> 4)] * sf[shift + OFF1 + (p & 15)];
        }
        __syncthreads();

        // --- order 4: f4[m] = f3[k] * x[j] ---
        #pragma unroll
        for (int m = t; m < N4; m += NTHREADS) {
            const uint16_t p = c_t4.v[m];
            sf[shift + OFF4 + m] =
                sf[shift + OFF3 + (p >> 4)] * sf[shift + OFF1 + (p & 15)];
        }
        __syncthreads();

        // --- flush: scalar head, aligned float4 body, scalar tail ---
        float* __restrict__ o = out + gbase;
        const int head = (4 - shift) & 3;     // first 16B-aligned channel
        if (t < head) o[t] = sf[shift + t];

        const int nv = (NOUT - head) >> 2;
        // (shift + head) is a multiple of 4 -> 16B-aligned smem source.
        const float4* __restrict__ sv = (const float4*)(sf + shift + head);
        float4* __restrict__ ov = (float4*)(o + head);
        #pragma unroll
        for (int q = t; q < nv; q += NTHREADS) ov[q] = sv[q];

        const int done = head + 4 * nv;
        if (t < NOUT - done) o[done + t] = sf[shift + done + t];
        __syncthreads();   // sf reused next row
    }
}

extern "C" void kernel_launch(void* const* d_in, const int* in_sizes, int n_in,
                              void* d_out, int out_size) {
    const float* in = (const float*)d_in[0];
    float* out = (float*)d_out;
    const int rows = in_sizes[0] / D;          // 4 * 2048 = 8192
    const int grid = (rows + RPB - 1) / RPB;   // 1024
    Moment_2774548873409_kernel<<<grid, NTHREADS>>>(in, out, rows);
}

// round 3
// speedup vs baseline: 1.2082x; 1.2082x over previous
#include <cuda_runtime.h>
#include <cstdint>

// Moment feature expansion, order 4, latent dim 16.
// out[b,t,:] = [1, x(16), f2(136), f3(816), f4(3876)] -> 4845 channels.
// Round 3: 1 row/block (occ ~89%, small smem). Orders 0-3 staged in a
// phase-shifted smem buffer and flushed as aligned float4; order 4 computed
// 4-per-thread and stored directly with aligned STG.128 (scalar head/tail).

#define D    16
#define N2   136
#define N3   816
#define N4   3876
#define NOUT 4845
#define OFF1 1
#define OFF2 17     // 1 + 16
#define OFF3 153    // 1 + 16 + 136
#define NLOW 969    // channels in orders 0..3

#define NTHREADS 256

struct Tab2 { uint16_t v[N2]; };
struct Tab3 { uint16_t v[N3]; };
struct Tab4 { uint16_t v[N4]; };

constexpr Tab2 gen2() {
    Tab2 t{}; int m = 0;
    for (int k = 0; k < D; k++)
        for (int j = 0; j <= k; j++)
            t.v[m++] = (uint16_t)((k << 4) | j);
    return t;
}
constexpr Tab3 gen3() {
    Tab3 t{}; int m = 0;
    int off[D] = {};
    for (int j = 0; j < D; j++)
        off[j] = N2 - (D - j) * (D - j + 1) / 2;
    for (int k = 0; k < N2; k++)
        for (int j = 0; j < D; j++)
            if (k >= off[j]) t.v[m++] = (uint16_t)((k << 4) | j);
    return t;
}
constexpr Tab4 gen4() {
    Tab4 t{}; int m = 0;
    int off[D] = {};
    for (int j = 0; j < D; j++) {
        int a = D + 2 - j;                      // 18 - j
        off[j] = N3 - a * (a - 1) * (a - 2) / 6;
    }
    for (int k = 0; k < N3; k++)
        for (int j = 0; j < D; j++)
            if (k >= off[j]) t.v[m++] = (uint16_t)((k << 4) | j);
    return t;
}

__device__ constexpr Tab2 c_t2 = gen2();
__device__ constexpr Tab3 c_t3 = gen3();
__device__ constexpr Tab4 c_t4 = gen4();

__global__ __launch_bounds__(NTHREADS)
void Moment_2774548873409_kernel(const float* __restrict__ in,
                                 float* __restrict__ out,
                                 int rows) {
    // Orders 0..3 staged here, phase-shifted so smem idx == gmem idx (mod 4).
    __shared__ __align__(16) float sf[NLOW + 4];

    const int row = blockIdx.x;
    if (row >= rows) return;
    const int t = threadIdx.x;

    const size_t gbase = (size_t)row * NOUT;
    const int shift = (int)(gbase & 3);          // == row & 3  (4845 % 4 == 1)
    const float* __restrict__ xin = in + (size_t)row * D;

    // --- orders 0, 1 ---
    if (t == 0) sf[shift] = 1.0f;
    if (t < D)  sf[shift + OFF1 + t] = xin[t];
    __syncthreads();

    // --- order 2 ---
    if (t < N2) {
        const uint16_t p = c_t2.v[t];
        sf[shift + OFF2 + t] =
            sf[shift + OFF1 + (p >> 4)] * sf[shift + OFF1 + (p & 15)];
    }
    __syncthreads();

    // --- order 3 ---
    #pragma unroll
    for (int m = t; m < N3; m += NTHREADS) {
        const uint16_t p = c_t3.v[m];
        sf[shift + OFF3 + m] =
            sf[shift + OFF2 + (p >> 4)] * sf[shift + OFF1 + (p & 15)];
    }
    __syncthreads();

    // ================= order 4: direct to GMEM, aligned STG.128 =============
    float* __restrict__ o4 = out + gbase + NLOW;
    const int a4    = (int)((gbase + NLOW) & 3);
    const int head4 = (4 - a4) & 3;              // scalar prologue elements

    if (t < head4) {
        const uint16_t p = c_t4.v[t];
        o4[t] = sf[shift + OFF3 + (p >> 4)] * sf[shift + OFF1 + (p & 15)];
    }

    const int nv4 = (N4 - head4) >> 2;           // aligned float4 groups
    float4* __restrict__ ov4 = (float4*)(o4 + head4);
    #pragma unroll 4
    for (int g = t; g < nv4; g += NTHREADS) {
        const int m0 = head4 + 4 * g;
        const uint16_t p0 = c_t4.v[m0 + 0];
        const uint16_t p1 = c_t4.v[m0 + 1];
        const uint16_t p2 = c_t4.v[m0 + 2];
        const uint16_t p3 = c_t4.v[m0 + 3];
        float4 v;
        v.x = sf[shift + OFF3 + (p0 >> 4)] * sf[shift + OFF1 + (p0 & 15)];
        v.y = sf[shift + OFF3 + (p1 >> 4)] * sf[shift + OFF1 + (p1 & 15)];
        v.z = sf[shift + OFF3 + (p2 >> 4)] * sf[shift + OFF1 + (p2 & 15)];
        v.w = sf[shift + OFF3 + (p3 >> 4)] * sf[shift + OFF1 + (p3 & 15)];
        ov4[g] = v;
    }

    const int done4 = head4 + 4 * nv4;
    if (t < N4 - done4) {
        const int m = done4 + t;
        const uint16_t p = c_t4.v[m];
        o4[m] = sf[shift + OFF3 + (p >> 4)] * sf[shift + OFF1 + (p & 15)];
    }

    // ================= flush orders 0..3 (969 floats), aligned float4 =======
    float* __restrict__ o = out + gbase;
    const int head = (4 - shift) & 3;
    if (t < head) o[t] = sf[shift + t];

    const int nv = (NLOW - head) >> 2;
    const float4* __restrict__ sv = (const float4*)(sf + shift + head);
    float4* __restrict__ ov = (float4*)(o + head);
    #pragma unroll 4
    for (int q = t; q < nv; q += NTHREADS) ov[q] = sv[q];

    const int done = head + 4 * nv;
    if (t < NLOW - done) o[done + t] = sf[shift + done + t];
}

extern "C" void kernel_launch(void* const* d_in, const int* in_sizes, int n_in,
                              void* d_out, int out_size) {
    const float* in = (const float*)d_in[0];
    float* out = (float*)d_out;
    const int rows = in_sizes[0] / D;            // 8192
    Moment_2774548873409_kernel<<<rows, NTHREADS>>>(in, out, rows);
}

// round 4
// speedup vs baseline: 1.2783x; 1.0580x over previous
#include <cuda_runtime.h>
#include <cstdint>

// Moment feature expansion, order 4, latent dim 16.
// out[b,t,:] = [1, x(16), f2(136), f3(816), f4(3876)] -> 4845 channels.
// Round 4: 1 row/block. Orders 0-3 staged in phase-shifted smem (float4
// flush). Order 4: per-alignment-phase precomputed group tables of packed
// smem BYTE offsets -> per 4 outputs: 1 LDG.128 + 8 LDS + 4 FMUL + 1 STG.128.

#define D    16
#define N2   136
#define N3   816
#define N4   3876
#define NOUT 4845
#define OFF1 1
#define OFF2 17     // 1 + 16
#define OFF3 153    // 1 + 16 + 136
#define NLOW 969    // orders 0..3

#define NTHREADS 256
#define MAXG 969    // max float4 groups in f4 (phase 0)

struct Tab2 { uint16_t v[N2]; };
struct Tab3 { uint16_t v[N3]; };
struct Tab4 { uint16_t v[N4]; };
struct Grp4 { uint32_t v[4][MAXG * 4]; };   // [phase][g*4+e] packed offsets

constexpr Tab2 gen2() {
    Tab2 t{}; int m = 0;
    for (int k = 0; k < D; k++)
        for (int j = 0; j <= k; j++)
            t.v[m++] = (uint16_t)((k << 4) | j);
    return t;
}
constexpr Tab3 gen3() {
    Tab3 t{}; int m = 0;
    int off[D] = {};
    for (int j = 0; j < D; j++)
        off[j] = N2 - (D - j) * (D - j + 1) / 2;
    for (int k = 0; k < N2; k++)
        for (int j = 0; j < D; j++)
            if (k >= off[j]) t.v[m++] = (uint16_t)((k << 4) | j);
    return t;
}
constexpr Tab4 gen4() {
    Tab4 t{}; int m = 0;
    int off[D] = {};
    for (int j = 0; j < D; j++) {
        int a = D + 2 - j;                       // 18 - j
        off[j] = N3 - a * (a - 1) * (a - 2) / 6;
    }
    for (int k = 0; k < N3; k++)
        for (int j = 0; j < D; j++)
            if (k >= off[j]) t.v[m++] = (uint16_t)((k << 4) | j);
    return t;
}

// Per-phase group tables: packed = (xByteOff << 16) | f3ByteOff, offsets are
// bytes relative to sf + shift (i.e., channel index * 4).
constexpr Grp4 genG() {
    Grp4 t{};
    int off[D] = {};
    for (int j = 0; j < D; j++) {
        int a = D + 2 - j;
        off[j] = N3 - a * (a - 1) * (a - 2) / 6;
    }
    uint16_t kk[N4] = {}, jj[N4] = {};
    int m = 0;
    for (int k = 0; k < N3; k++)
        for (int j = 0; j < D; j++)
            if (k >= off[j]) { kk[m] = (uint16_t)k; jj[m] = (uint16_t)j; m++; }
    for (int h = 0; h < 4; h++) {
        int nv = (N4 - h) >> 2;
        for (int g = 0; g < nv; g++)
            for (int e = 0; e < 4; e++) {
                int mm = h + 4 * g + e;
                uint32_t f3off = (uint32_t)(OFF3 + kk[mm]) * 4u;
                uint32_t xoff  = (uint32_t)(OFF1 + jj[mm]) * 4u;
                t.v[h][g * 4 + e] = (xoff << 16) | f3off;
            }
    }
    return t;
}

__device__ constexpr Tab2 c_t2 = gen2();
__device__ constexpr Tab3 c_t3 = gen3();
__device__ constexpr Tab4 c_t4 = gen4();
__device__ __align__(16) constexpr Grp4 c_g4 = genG();

__device__ __forceinline__ float pmul(uint32_t pw, const char* sfb) {
    float a = *(const float*)(sfb + (pw & 0xFFFFu));
    float b = *(const float*)(sfb + (pw >> 16));
    return a * b;
}

__global__ __launch_bounds__(NTHREADS)
void Moment_2774548873409_kernel(const float* __restrict__ in,
                                 float* __restrict__ out,
                                 int rows) {
    __shared__ __align__(16) float sf[NLOW + 4];

    const int row = blockIdx.x;
    if (row >= rows) return;
    const int t = threadIdx.x;

    const size_t gbase = (size_t)row * NOUT;
    const int shift = (int)(gbase & 3);          // == row & 3 (4845 % 4 == 1)
    const float* __restrict__ xin = in + (size_t)row * D;

    // --- orders 0, 1 ---
    if (t == 0) sf[shift] = 1.0f;
    if (t < D)  sf[shift + OFF1 + t] = xin[t];
    __syncthreads();

    // --- order 2 ---
    if (t < N2) {
        const uint16_t p = c_t2.v[t];
        sf[shift + OFF2 + t] =
            sf[shift + OFF1 + (p >> 4)] * sf[shift + OFF1 + (p & 15)];
    }
    __syncthreads();

    // --- order 3 ---
    #pragma unroll
    for (int m = t; m < N3; m += NTHREADS) {
        const uint16_t p = c_t3.v[m];
        sf[shift + OFF3 + m] =
            sf[shift + OFF2 + (p >> 4)] * sf[shift + OFF1 + (p & 15)];
    }
    __syncthreads();

    const char* sfb = (const char*)sf + 4 * shift;   // byte base incl. phase

    // ============== order 4: group table, LDG.128 + STG.128 ================
    float* __restrict__ o4 = out + gbase + NLOW;
    const int a4 = (int)((gbase + NLOW) & 3);
    const int h  = (4 - a4) & 3;                 // scalar head count

    if (t < h) {
        const uint16_t p = c_t4.v[t];
        o4[t] = *(const float*)(sfb + (OFF3 + (p >> 4)) * 4) *
                *(const float*)(sfb + (OFF1 + (p & 15)) * 4);
    }

    const int nv = (N4 - h) >> 2;
    const uint4* __restrict__ gt = (const uint4*)&c_g4.v[h][0];
    float4* __restrict__ ov = (float4*)(o4 + h);
    #pragma unroll 4
    for (int g = t; g < nv; g += NTHREADS) {
        const uint4 w = gt[g];
        float4 v;
        v.x = pmul(w.x, sfb);
        v.y = pmul(w.y, sfb);
        v.z = pmul(w.z, sfb);
        v.w = pmul(w.w, sfb);
        ov[g] = v;
    }

    const int done = h + 4 * nv;
    if (t < N4 - done) {
        const int m = done + t;
        const uint16_t p = c_t4.v[m];
        o4[m] = *(const float*)(sfb + (OFF3 + (p >> 4)) * 4) *
                *(const float*)(sfb + (OFF1 + (p & 15)) * 4);
    }

    // ============== flush orders 0..3 (969 floats), aligned float4 ==========
    float* __restrict__ o = out + gbase;
    const int head = (4 - shift) & 3;
    if (t < head) o[t] = sf[shift + t];

    const int nvl = (NLOW - head) >> 2;
    const float4* __restrict__ sv = (const float4*)(sf + shift + head);
    float4* __restrict__ ovl = (float4*)(o + head);
    #pragma unroll
    for (int q = t; q < nvl; q += NTHREADS) ovl[q] = sv[q];

    const int dl = head + 4 * nvl;
    if (t < NLOW - dl) o[dl + t] = sf[shift + dl + t];
}

extern "C" void kernel_launch(void* const* d_in, const int* in_sizes, int n_in,
                              void* d_out, int out_size) {
    const float* in = (const float*)d_in[0];
    float* out = (float*)d_out;
    const int rows = in_sizes[0] / D;            // 8192
    Moment_2774548873409_kernel<<<rows, NTHREADS>>>(in, out, rows);
}

// round 5
// speedup vs baseline: 1.3441x; 1.0515x over previous
#include <cuda_runtime.h>
#include <cstdint>

// Moment feature expansion, order 4, latent dim 16.
// out[b,t,:] = [1, x(16), f2(136), f3(816), f4(3876)] -> 4845 channels.
// Round 5: f4 computed pair-wise. Consecutive f4 elements satisfy
// k_b-k_a in {0,1}, j_b in {j_a+1, 0}. One LDS.64 on parity-replicated f3
// gives both f3 operands, one LDS.64 on replicated x gives both x operands
// (x[0] register-cached for run resets); 1-bit SELs pick. Table: u32/pair.

#define D    16
#define N2   136
#define N3   816
#define N4   3876
#define NOUT 4845
#define OFF1 1
#define OFF2 17
#define OFF3 153
#define NLOW 969

#define NTHREADS 256
#define MAXG 969          // max float4 groups (phase 0)
#define F3STRIDE 817      // floats per f3 copy (816 + 1 pad)
#define F3COPYB  3268     // bytes per f3 copy (== 4 mod 8)
#define XSTRIDE  17       // floats per x copy (16 + 1 pad)
#define XCOPYB   68       // bytes per x copy (== 4 mod 8)

struct Tab2 { uint16_t v[N2]; };
struct Tab3 { uint16_t v[N3]; };
struct Tab4 { uint16_t v[N4]; };
struct Grp4 { uint32_t v[4][MAXG * 2]; };   // [phase][group*2 + pair]

constexpr Tab2 gen2() {
    Tab2 t{}; int m = 0;
    for (int k = 0; k < D; k++)
        for (int j = 0; j <= k; j++)
            t.v[m++] = (uint16_t)((k << 4) | j);
    return t;
}
constexpr Tab3 gen3() {
    Tab3 t{}; int m = 0;
    int off[D] = {};
    for (int j = 0; j < D; j++)
        off[j] = N2 - (D - j) * (D - j + 1) / 2;
    for (int k = 0; k < N2; k++)
        for (int j = 0; j < D; j++)
            if (k >= off[j]) t.v[m++] = (uint16_t)((k << 4) | j);
    return t;
}
constexpr Tab4 gen4() {
    Tab4 t{}; int m = 0;
    int off[D] = {};
    for (int j = 0; j < D; j++) {
        int a = D + 2 - j;                       // 18 - j
        off[j] = N3 - a * (a - 1) * (a - 2) / 6;
    }
    for (int k = 0; k < N3; k++)
        for (int j = 0; j < D; j++)
            if (k >= off[j]) t.v[m++] = (uint16_t)((k << 4) | j);
    return t;
}

// Pair word: [12:0]=f3 byte off (incl. parity copy), [20:13]=x byte off
// (incl. parity copy), [21]=ksel (k_b==k_a+1), [22]=xsel (j_b==j_a+1).
constexpr Grp4 genG() {
    Grp4 t{};
    int off[D] = {};
    for (int j = 0; j < D; j++) {
        int a = D + 2 - j;
        off[j] = N3 - a * (a - 1) * (a - 2) / 6;
    }
    uint16_t kk[N4] = {}, jj[N4] = {};
    int m = 0;
    for (int k = 0; k < N3; k++)
        for (int j = 0; j < D; j++)
            if (k >= off[j]) { kk[m] = (uint16_t)k; jj[m] = (uint16_t)j; m++; }
    for (int h = 0; h < 4; h++) {
        int nv = (N4 - h) >> 2;
        for (int g = 0; g < nv; g++)
            for (int pr = 0; pr < 2; pr++) {
                int a = h + 4 * g + 2 * pr, b = a + 1;
                uint32_t ka = kk[a], ja = jj[a];
                uint32_t o3 = (ka & 1u) * F3COPYB + 4u * ka;      // 8B aligned
                uint32_t ox = (ja & 1u) * XCOPYB  + 4u * ja;      // 8B aligned
                uint32_t ks = (kk[b] != ka) ? 1u : 0u;
                uint32_t xs = (jj[b] == ja + 1) ? 1u : 0u;
                t.v[h][2 * g + pr] = o3 | (ox << 13) | (ks << 21) | (xs << 22);
            }
    }
    return t;
}

__device__ constexpr Tab2 c_t2 = gen2();
__device__ constexpr Tab3 c_t3 = gen3();
__device__ constexpr Tab4 c_t4 = gen4();
__device__ __align__(16) constexpr Grp4 c_g4 = genG();

__global__ __launch_bounds__(NTHREADS)
void Moment_2774548873409_kernel(const float* __restrict__ in,
                                 float* __restrict__ out,
                                 int rows) {
    __shared__ __align__(16) float sf[NLOW + 4];          // phase-shifted row
    __shared__ __align__(16) float f3r[2 * F3STRIDE];     // f3, 2 parity copies
    __shared__ __align__(16) float xr[2 * XSTRIDE];       // x,  2 parity copies

    const int row = blockIdx.x;
    if (row >= rows) return;
    const int t = threadIdx.x;

    const size_t gbase = (size_t)row * NOUT;
    const int shift = (int)(gbase & 3);          // 4845 % 4 == 1 -> row & 3
    const float* __restrict__ xin = in + (size_t)row * D;

    // --- orders 0, 1 ---
    if (t == 0) {
        sf[shift] = 1.0f;
        f3r[N3] = 0.0f; f3r[F3STRIDE + N3] = 0.0f;   // pads
        xr[D] = 0.0f;   xr[XSTRIDE + D] = 0.0f;
    }
    if (t < D) {
        const float v = xin[t];
        sf[shift + OFF1 + t] = v;
        xr[t] = v; xr[XSTRIDE + t] = v;
    }
    __syncthreads();
    const float x0 = xr[0];

    // --- order 2 ---
    if (t < N2) {
        const uint16_t p = c_t2.v[t];
        sf[shift + OFF2 + t] =
            sf[shift + OFF1 + (p >> 4)] * sf[shift + OFF1 + (p & 15)];
    }
    __syncthreads();

    // --- order 3 (written to sf for flush + both parity copies for f4) ---
    #pragma unroll
    for (int m = t; m < N3; m += NTHREADS) {
        const uint16_t p = c_t3.v[m];
        const float v =
            sf[shift + OFF2 + (p >> 4)] * sf[shift + OFF1 + (p & 15)];
        sf[shift + OFF3 + m] = v;
        f3r[m] = v; f3r[F3STRIDE + m] = v;
    }
    __syncthreads();

    const char* __restrict__ f3b = (const char*)f3r;
    const char* __restrict__ xb  = (const char*)xr;
    const char* __restrict__ sfb = (const char*)sf + 4 * shift;

    // ================= order 4: pairwise LDS.64 + STG.128 ==================
    float* __restrict__ o4 = out + gbase + NLOW;
    const int a4 = (int)((gbase + NLOW) & 3);
    const int h  = (4 - a4) & 3;

    if (t < h) {
        const uint16_t p = c_t4.v[t];
        o4[t] = *(const float*)(sfb + (OFF3 + (p >> 4)) * 4) *
                *(const float*)(sfb + (OFF1 + (p & 15)) * 4);
    }

    const int nv = (N4 - h) >> 2;
    const uint2* __restrict__ gt = (const uint2*)&c_g4.v[h][0];
    float4* __restrict__ ov = (float4*)(o4 + h);
    #pragma unroll 4
    for (int g = t; g < nv; g += NTHREADS) {
        const uint2 w = gt[g];
        float4 r;
        {
            const uint32_t u = w.x;
            const float2 f  = *(const float2*)(f3b + (u & 0x1FFFu));
            const float2 xv = *(const float2*)(xb + ((u >> 13) & 0xFFu));
            r.x = f.x * xv.x;
            const float fb = (u & (1u << 21)) ? f.y : f.x;
            const float vb = (u & (1u << 22)) ? xv.y : x0;
            r.y = fb * vb;
        }
        {
            const uint32_t u = w.y;
            const float2 f  = *(const float2*)(f3b + (u & 0x1FFFu));
            const float2 xv = *(const float2*)(xb + ((u >> 13) & 0xFFu));
            r.z = f.x * xv.x;
            const float fb = (u & (1u << 21)) ? f.y : f.x;
            const float vb = (u & (1u << 22)) ? xv.y : x0;
            r.w = fb * vb;
        }
        ov[g] = r;
    }

    const int done = h + 4 * nv;
    if (t < N4 - done) {
        const int m = done + t;
        const uint16_t p = c_t4.v[m];
        o4[m] = *(const float*)(sfb + (OFF3 + (p >> 4)) * 4) *
                *(const float*)(sfb + (OFF1 + (p & 15)) * 4);
    }

    // ================= flush orders 0..3 (969 floats) =======================
    float* __restrict__ o = out + gbase;
    const int head = (4 - shift) & 3;
    if (t < head) o[t] = sf[shift + t];

    const int nvl = (NLOW - head) >> 2;
    const float4* __restrict__ sv = (const float4*)(sf + shift + head);
    float4* __restrict__ ovl = (float4*)(o + head);
    #pragma unroll
    for (int q = t; q < nvl; q += NTHREADS) ovl[q] = sv[q];

    const int dl = head + 4 * nvl;
    if (t < NLOW - dl) o[dl + t] = sf[shift + dl + t];
}

extern "C" void kernel_launch(void* const* d_in, const int* in_sizes, int n_in,
                              void* d_out, int out_size) {
    const float* in = (const float*)d_in[0];
    float* out = (float*)d_out;
    const int rows = in_sizes[0] / D;            // 8192
    Moment_2774548873409_kernel<<<rows, NTHREADS>>>(in, out, rows);
}

// round 6
// speedup vs baseline: 1.3703x; 1.0194x over previous
#include <cuda_runtime.h>
#include <cstdint>

// Moment feature expansion, order 4, latent dim 16.
// out[b,t,:] = [1, x(16), f2(136), f3(816), f4(3876)] -> 4845 channels.
// Round 6: no staging buffer / no flush pass -- every stage stores its own
// gmem segment directly. Order-3 and order-4 both computed pairwise:
// consecutive elements share the run structure (k same-or+1, j -> j+1 or 0),
// so one LDS.64 on a parity-replicated operand array + selects covers a pair.

#define D    16
#define N2   136
#define N3   816
#define N4   3876
#define NOUT 4845
#define NTHREADS 256

#define F2S 137      // floats per f2 copy; copy1 base = 548 B == 4 (mod 8)
#define F3S 817      // floats per f3 copy; copy1 base = 3268 B == 4 (mod 8)
#define XS  17       // floats per x  copy; copy1 base = 68 B == 4 (mod 8)
#define MAXG 969     // max float4 groups in f4 (phase 0)

struct Tab2 { uint16_t v[N2]; };
struct Tab4 { uint16_t v[N4]; };
struct Tp3  { uint32_t v[2][408]; };        // [row-parity phase][pair]
struct Grp4 { uint32_t v[4][MAXG * 2]; };   // [gmem phase][group*2 + pair]

constexpr Tab2 gen2() {
    Tab2 t{}; int m = 0;
    for (int k = 0; k < D; k++)
        for (int j = 0; j <= k; j++)
            t.v[m++] = (uint16_t)((k << 4) | j);
    return t;
}

constexpr Tab4 gen4() {
    Tab4 t{}; int m = 0;
    int off[D] = {};
    for (int j = 0; j < D; j++) {
        int a = D + 2 - j;                       // 18 - j
        off[j] = N3 - a * (a - 1) * (a - 2) / 6;
    }
    for (int k = 0; k < N3; k++)
        for (int j = 0; j < D; j++)
            if (k >= off[j]) t.v[m++] = (uint16_t)((k << 4) | j);
    return t;
}

// Order-3 pair table. Word: [10:0]=f2 byte off (incl. parity copy),
// [18:11]=x byte off (incl. parity copy), [20]=ksel, [21]=xsel.
constexpr Tp3 genP3() {
    Tp3 t{};
    int off[D] = {};
    for (int j = 0; j < D; j++)
        off[j] = N2 - (D - j) * (D - j + 1) / 2;
    uint16_t kk[N3] = {}, jj[N3] = {};
    int m = 0;
    for (int k = 0; k < N2; k++)
        for (int j = 0; j < D; j++)
            if (k >= off[j]) { kk[m] = (uint16_t)k; jj[m] = (uint16_t)j; m++; }
    for (int h = 0; h < 2; h++) {
        int np = (N3 - h) / 2;                   // 408 or 407
        for (int p = 0; p < np; p++) {
            int a = h + 2 * p, b = a + 1;
            uint32_t k2 = kk[a], j = jj[a];
            uint32_t o2 = (k2 & 1u) * (F2S * 4u) + 4u * k2;
            uint32_t ox = (j & 1u) * (XS * 4u) + 4u * j;
            uint32_t ks = (kk[b] != k2) ? 1u : 0u;
            uint32_t xs = (jj[b] == j + 1) ? 1u : 0u;
            t.v[h][p] = o2 | (ox << 11) | (ks << 20) | (xs << 21);
        }
    }
    return t;
}

// Order-4 pair table per gmem alignment phase. Word: [12:0]=f3 byte off
// (incl. parity copy), [20:13]=x byte off (incl. parity copy), [21]=ksel,
// [22]=xsel.
constexpr Grp4 genG() {
    Grp4 t{};
    int off[D] = {};
    for (int j = 0; j < D; j++) {
        int a = D + 2 - j;
        off[j] = N3 - a * (a - 1) * (a - 2) / 6;
    }
    uint16_t kk[N4] = {}, jj[N4] = {};
    int m = 0;
    for (int k = 0; k < N3; k++)
        for (int j = 0; j < D; j++)
            if (k >= off[j]) { kk[m] = (uint16_t)k; jj[m] = (uint16_t)j; m++; }
    for (int h = 0; h < 4; h++) {
        int nv = (N4 - h) >> 2;
        for (int g = 0; g < nv; g++)
            for (int pr = 0; pr < 2; pr++) {
                int a = h + 4 * g + 2 * pr, b = a + 1;
                uint32_t ka = kk[a], ja = jj[a];
                uint32_t o3 = (ka & 1u) * (F3S * 4u) + 4u * ka;   // 8B aligned
                uint32_t ox = (ja & 1u) * (XS * 4u) + 4u * ja;    // 8B aligned
                uint32_t ks = (kk[b] != ka) ? 1u : 0u;
                uint32_t xs = (jj[b] == ja + 1) ? 1u : 0u;
                t.v[h][2 * g + pr] = o3 | (ox << 13) | (ks << 21) | (xs << 22);
            }
    }
    return t;
}

__device__ constexpr Tab2 c_t2 = gen2();
__device__ constexpr Tab4 c_t4 = gen4();
__device__ __align__(8)  constexpr Tp3  c_p3 = genP3();
__device__ __align__(16) constexpr Grp4 c_g4 = genG();

__global__ __launch_bounds__(NTHREADS)
void Moment_2774548873409_kernel(const float* __restrict__ in,
                                 float* __restrict__ out,
                                 int rows) {
    __shared__ __align__(16) float f3r[2 * F3S];   // f3, 2 parity copies
    __shared__ __align__(16) float f2r[2 * F2S];   // f2, 2 parity copies
    __shared__ __align__(16) float xr[2 * XS];     // x,  2 parity copies

    const int row = blockIdx.x;
    if (row >= rows) return;
    const int t = threadIdx.x;

    const size_t gbase = (size_t)row * NOUT;
    float* __restrict__ o = out + gbase;
    const float* __restrict__ xin = in + (size_t)row * D;

    // --- orders 0, 1 ---
    if (t < D) {
        const float v = xin[t];
        xr[t] = v; xr[XS + t] = v;
        o[1 + t] = v;
    }
    if (t == 0) o[0] = 1.0f;
    __syncthreads();
    const float x0 = xr[0];

    // --- order 2: f2[m] = x[k] * x[j], direct store ---
    if (t < N2) {
        const uint16_t p = c_t2.v[t];
        const float v = xr[p >> 4] * xr[p & 15];
        f2r[t] = v; f2r[F2S + t] = v;
        o[17 + t] = v;
    }
    __syncthreads();

    const char* __restrict__ f2b = (const char*)f2r;
    const char* __restrict__ xb  = (const char*)xr;

    // --- order 3: pairwise, direct float2 store (always 8B-aligned) ---
    const int h3 = (int)((gbase + 153) & 1);
    if (h3 == 0) {
        #pragma unroll 2
        for (int p = t; p < 408; p += NTHREADS) {
            const uint32_t w = c_p3.v[0][p];
            const float2 f  = *(const float2*)(f2b + (w & 0x7FFu));
            const float2 xv = *(const float2*)(xb + ((w >> 11) & 0xFFu));
            const float e0 = f.x * xv.x;
            const float e1 = ((w & (1u << 20)) ? f.y : f.x) *
                             ((w & (1u << 21)) ? xv.y : x0);
            const int m = 2 * p;
            *(float2*)(f3r + m) = make_float2(e0, e1);       // copy0 aligned
            f3r[F3S + m] = e0; f3r[F3S + m + 1] = e1;        // copy1 scalar
            *(float2*)(o + 153 + m) = make_float2(e0, e1);
        }
    } else {
        #pragma unroll 2
        for (int p = t; p < 407; p += NTHREADS) {
            const uint32_t w = c_p3.v[1][p];
            const float2 f  = *(const float2*)(f2b + (w & 0x7FFu));
            const float2 xv = *(const float2*)(xb + ((w >> 11) & 0xFFu));
            const float e0 = f.x * xv.x;
            const float e1 = ((w & (1u << 20)) ? f.y : f.x) *
                             ((w & (1u << 21)) ? xv.y : x0);
            const int m = 1 + 2 * p;
            f3r[m] = e0; f3r[m + 1] = e1;                    // copy0 scalar
            *(float2*)(f3r + F3S + m) = make_float2(e0, e1); // copy1 aligned
            *(float2*)(o + 153 + m) = make_float2(e0, e1);
        }
        if (t == 0) {            // f3[0] = f2[0] * x0
            const float v = f2r[0] * x0;
            f3r[0] = v; f3r[F3S] = v; o[153] = v;
        }
        if (t == 1) {            // f3[815] = f2[135] * x[15]
            const float v = f2r[135] * xr[15];
            f3r[815] = v; f3r[F3S + 815] = v; o[153 + 815] = v;
        }
    }
    __syncthreads();

    // --- order 4: pairwise LDS.64 + aligned STG.128 (R5 scheme) ---
    const char* __restrict__ f3b = (const char*)f3r;
    float* __restrict__ o4 = o + 969;
    const int a4 = (int)((gbase + 969) & 3);
    const int h  = (4 - a4) & 3;

    if (t < h) {
        const uint16_t p = c_t4.v[t];
        o4[t] = f3r[p >> 4] * xr[p & 15];
    }

    const int nv = (N4 - h) >> 2;
    const uint2* __restrict__ gt = (const uint2*)&c_g4.v[h][0];
    float4* __restrict__ ov = (float4*)(o4 + h);
    #pragma unroll 4
    for (int g = t; g < nv; g += NTHREADS) {
        const uint2 w = gt[g];
        float4 r;
        {
            const uint32_t u = w.x;
            const float2 f  = *(const float2*)(f3b + (u & 0x1FFFu));
            const float2 xv = *(const float2*)(xb + ((u >> 13) & 0xFFu));
            r.x = f.x * xv.x;
            r.y = ((u & (1u << 21)) ? f.y : f.x) *
                  ((u & (1u << 22)) ? xv.y : x0);
        }
        {
            const uint32_t u = w.y;
            const float2 f  = *(const float2*)(f3b + (u & 0x1FFFu));
            const float2 xv = *(const float2*)(xb + ((u >> 13) & 0xFFu));
            r.z = f.x * xv.x;
            r.w = ((u & (1u << 21)) ? f.y : f.x) *
                  ((u & (1u << 22)) ? xv.y : x0);
        }
        ov[g] = r;
    }

    const int done = h + 4 * nv;
    if (t < N4 - done) {
        const int m = done + t;
        const uint16_t p = c_t4.v[m];
        o4[m] = f3r[p >> 4] * xr[p & 15];
    }
}

extern "C" void kernel_launch(void* const* d_in, const int* in_sizes, int n_in,
                              void* d_out, int out_size) {
    const float* in = (const float*)d_in[0];
    float* out = (float*)d_out;
    const int rows = in_sizes[0] / D;            // 8192
    Moment_2774548873409_kernel<<<rows, NTHREADS>>>(in, out, rows);
}